// round 10
// baseline (speedup 1.0000x reference)
#include <cuda_runtime.h>
#include <cuda_bf16.h>
#include <math.h>
#include <stdint.h>

#define DMODEL 1024
#define NHEADS 16
#define DK 64
#define BB 2
#define SS 2048
#define NTOK (BB*SS)

// fp32 scratch
__device__ float g_Q[NTOK*DMODEL];   // [B*H, S, DK] head-major
__device__ float g_K[NTOK*DMODEL];   // [B*H, S, DK]
__device__ float g_V[NTOK*DMODEL];   // [B*H, S, DK]
__device__ float g_C[NTOK*DMODEL];   // [B, S, H*DK] token-major

// pre-split bf16 operands (bf16x2 packs as uint32)
#define APAIRS (NTOK*DMODEL/2)       // 2,097,152 pairs per activation matrix
#define WPAIRS (DMODEL*DMODEL/2)     // 524,288 pairs per weight matrix
__device__ uint32_t g_Ah[3*APAIRS];  // q,k,v hi
__device__ uint32_t g_Al[3*APAIRS];  // q,k,v lo
__device__ uint32_t g_Wh[4*WPAIRS];  // Wq,Wk,Wv,Wo hi
__device__ uint32_t g_Wl[4*WPAIRS];  // lo
__device__ uint32_t g_Chp[APAIRS];   // context hi
__device__ uint32_t g_Clp[APAIRS];   // context lo

// ===========================================================================
// helpers
// ===========================================================================
__device__ __forceinline__ uint32_t smem_u32(const void* p) {
    uint32_t a;
    asm("{ .reg .u64 t; cvta.to.shared.u64 t, %1; cvt.u32.u64 %0, t; }"
        : "=r"(a) : "l"(p));
    return a;
}

__device__ __forceinline__ void ldsm_x4(uint32_t& r0, uint32_t& r1,
                                        uint32_t& r2, uint32_t& r3, uint32_t addr) {
    asm volatile("ldmatrix.sync.aligned.m8n8.x4.shared.b16 {%0,%1,%2,%3}, [%4];"
                 : "=r"(r0), "=r"(r1), "=r"(r2), "=r"(r3) : "r"(addr));
}

__device__ __forceinline__ void ldsm_x4_t(uint32_t& r0, uint32_t& r1,
                                          uint32_t& r2, uint32_t& r3, uint32_t addr) {
    asm volatile("ldmatrix.sync.aligned.m8n8.x4.trans.shared.b16 {%0,%1,%2,%3}, [%4];"
                 : "=r"(r0), "=r"(r1), "=r"(r2), "=r"(r3) : "r"(addr));
}

__device__ __forceinline__ void mma_bf16(float* c, const uint32_t* a, const uint32_t* b) {
    asm volatile(
        "mma.sync.aligned.m16n8k16.row.col.f32.bf16.bf16.f32 "
        "{%0,%1,%2,%3}, {%4,%5,%6,%7}, {%8,%9}, {%0,%1,%2,%3};"
        : "+f"(c[0]), "+f"(c[1]), "+f"(c[2]), "+f"(c[3])
        : "r"(a[0]), "r"(a[1]), "r"(a[2]), "r"(a[3]), "r"(b[0]), "r"(b[1]));
}

__device__ __forceinline__ void split2(float2 v, uint32_t& hp, uint32_t& lp) {
    asm("cvt.rn.bf16x2.f32 %0, %1, %2;" : "=r"(hp) : "f"(v.y), "f"(v.x));
    float h0 = __uint_as_float(hp << 16);
    float h1 = __uint_as_float(hp & 0xffff0000u);
    asm("cvt.rn.bf16x2.f32 %0, %1, %2;" : "=r"(lp) : "f"(v.y - h1), "f"(v.x - h0));
}

__device__ __forceinline__ uint32_t swz(int row, int chunk) {
    return (uint32_t)(row * 128 + ((chunk ^ (row & 7)) << 4));
}

#define CP16(dst, src) \
    asm volatile("cp.async.cg.shared.global [%0], [%1], 16;" \
        :: "r"(dst), "l"(src) : "memory")
#define CP_COMMIT() asm volatile("cp.async.commit_group;" ::: "memory")
#define CP_WAIT1()  asm volatile("cp.async.wait_group 1;" ::: "memory")
#define CP_WAIT0()  asm volatile("cp.async.wait_group 0;" ::: "memory")

// ===========================================================================
// Prep: split fp32 -> bf16 hi/lo in global memory (inputs + weights)
// ===========================================================================
__global__ __launch_bounds__(256) void convert_split_kernel(
    const float* __restrict__ q,  const float* __restrict__ k,  const float* __restrict__ v,
    const float* __restrict__ Wq, const float* __restrict__ Wk, const float* __restrict__ Wv,
    const float* __restrict__ Wo)
{
    const int z = blockIdx.y;
    const float* src;
    uint32_t *dh, *dl;
    int npairs;
    if (z < 3) {
        src = (z == 0) ? q : (z == 1) ? k : v;
        dh = g_Ah + (size_t)z * APAIRS; dl = g_Al + (size_t)z * APAIRS;
        npairs = APAIRS;
    } else {
        src = (z == 3) ? Wq : (z == 4) ? Wk : (z == 5) ? Wv : Wo;
        dh = g_Wh + (size_t)(z - 3) * WPAIRS; dl = g_Wl + (size_t)(z - 3) * WPAIRS;
        npairs = WPAIRS;
    }
    int i = blockIdx.x * 256 + threadIdx.x;
    if (i < npairs) {
        uint32_t hp, lp;
        split2(((const float2*)src)[i], hp, lp);
        dh[i] = hp; dl[i] = lp;
    }
}

__global__ __launch_bounds__(256) void convert_c_kernel()
{
    int i = blockIdx.x * 256 + threadIdx.x;
    uint32_t hp, lp;
    split2(((const float2*)g_C)[i], hp, lp);
    g_Chp[i] = hp; g_Clp[i] = lp;
}

// ===========================================================================
// Tensor-core GEMM on pre-split bf16: Y = X @ W^T + b.
// cp.async double-buffered, MMA-only inner loop.
// CTA tile 128x128, BK=64, 256 threads (8 warps, 2m x 4n).
// Stage = Ahi|Alo|Bhi|Blo, 16 KB each = 64 KB; 2 stages = 128 KB smem.
// ===========================================================================
#define NCHUNK 16
#define BUF16 16384
#define STAGE_B (4 * BUF16)
#define GEMM_SMEM (2 * STAGE_B)      // 128 KB

template<bool SPLIT>
__device__ __forceinline__ void gemm_tc_body(const uint32_t* __restrict__ Ah,
                                             const uint32_t* __restrict__ Al,
                                             const uint32_t* __restrict__ Bh,
                                             const uint32_t* __restrict__ Bl,
                                             const float* __restrict__ bias,
                                             float* __restrict__ Y)
{
    extern __shared__ char smc[];
    const uint32_t sbase = smem_u32(smc);

    const int tid = threadIdx.x;
    const int wid = tid >> 5, l = tid & 31;
    const int warp_m = (wid & 1) * 64;
    const int warp_n = (wid >> 1) * 32;
    const int m0 = blockIdx.y * 128, n0 = blockIdx.x * 128;

    // byte bases for this CTA's row panels (row stride = 2048 B)
    const char* Ahb = (const char*)Ah + (size_t)m0 * 2048;
    const char* Alb = (const char*)Al + (size_t)m0 * 2048;
    const char* Bhb = (const char*)Bh + (size_t)n0 * 2048;
    const char* Blb = (const char*)Bl + (size_t)n0 * 2048;

    // this thread's fixed slice of the stage load (4 x 16B per buffer)
    const int ld_row[4] = { (tid + 0) >> 3, (tid + 256) >> 3, (tid + 512) >> 3, (tid + 768) >> 3 };
    const int ld_chk[4] = { tid & 7, tid & 7, tid & 7, tid & 7 };

    float c[4][4][4];
#pragma unroll
    for (int i = 0; i < 4; i++)
#pragma unroll
        for (int j = 0; j < 4; j++)
#pragma unroll
            for (int t = 0; t < 4; t++) c[i][j][t] = 0.f;

    const int a_row_off = ((l >> 3) & 1) * 8 + (l & 7);
    const int a_chk_off = (l >> 4);
    const int b_row_off = ((l >> 4) & 1) * 8 + (l & 7);
    const int b_chk_off = ((l >> 3) & 1);

    // issue loads for a chunk into stage s
    auto issue = [&](int s, int ch) {
        const uint32_t sb = sbase + s * STAGE_B;
        const size_t coff = (size_t)ch * 128;   // 64 bf16 cols = 128 B
#pragma unroll
        for (int it = 0; it < 4; it++) {
            int row = ld_row[it], chunk = ld_chk[it];
            uint32_t d = swz(row, chunk);
            size_t so = (size_t)row * 2048 + coff + (size_t)(chunk << 4);
            CP16(sb + d,             Ahb + so);
            CP16(sb + BUF16 + d,     Alb + so);
            CP16(sb + 2*BUF16 + d,   Bhb + so);
            CP16(sb + 3*BUF16 + d,   Blb + so);
        }
        CP_COMMIT();
    };

    issue(0, 0);

    for (int ch = 0; ch < NCHUNK; ch++) {
        const int cur = ch & 1;
        if (ch + 1 < NCHUNK) { issue(cur ^ 1, ch + 1); CP_WAIT1(); }
        else                 { CP_WAIT0(); }
        __syncthreads();

        const uint32_t aAhi = sbase + cur * STAGE_B;
        const uint32_t aAlo = aAhi + BUF16;
        const uint32_t aBhi = aAhi + 2 * BUF16;
        const uint32_t aBlo = aAhi + 3 * BUF16;

#pragma unroll
        for (int ks = 0; ks < 4; ks++) {
            uint32_t ahi[4][4], alo[4][4], bhi[4][2], blo[4][2];
#pragma unroll
            for (int mi = 0; mi < 4; mi++) {
                int row = warp_m + mi * 16 + a_row_off;
                uint32_t o = swz(row, ks * 2 + a_chk_off);
                ldsm_x4(ahi[mi][0], ahi[mi][1], ahi[mi][2], ahi[mi][3], aAhi + o);
                ldsm_x4(alo[mi][0], alo[mi][1], alo[mi][2], alo[mi][3], aAlo + o);
            }
#pragma unroll
            for (int nj = 0; nj < 2; nj++) {
                int row = warp_n + nj * 16 + b_row_off;
                uint32_t o = swz(row, ks * 2 + b_chk_off);
                ldsm_x4(bhi[nj*2][0], bhi[nj*2][1], bhi[nj*2+1][0], bhi[nj*2+1][1], aBhi + o);
                ldsm_x4(blo[nj*2][0], blo[nj*2][1], blo[nj*2+1][0], blo[nj*2+1][1], aBlo + o);
            }
#pragma unroll
            for (int mi = 0; mi < 4; mi++)
#pragma unroll
                for (int ni = 0; ni < 4; ni++) {
                    mma_bf16(c[mi][ni], ahi[mi], bhi[ni]);
                    mma_bf16(c[mi][ni], ahi[mi], blo[ni]);
                    mma_bf16(c[mi][ni], alo[mi], bhi[ni]);
                }
        }
        __syncthreads();
    }

#pragma unroll
    for (int mi = 0; mi < 4; mi++)
#pragma unroll
        for (int ni = 0; ni < 4; ni++) {
            int colg = n0 + warp_n + ni * 8 + (l & 3) * 2;
            float2 bv = *(const float2*)&bias[colg];
            int r0 = m0 + warp_m + mi * 16 + (l >> 2);
#pragma unroll
            for (int half = 0; half < 2; half++) {
                int m = r0 + half * 8;
                float2 o2;
                o2.x = c[mi][ni][half * 2 + 0] + bv.x;
                o2.y = c[mi][ni][half * 2 + 1] + bv.y;
                if (SPLIT) {
                    int b = m >> 11, srow = m & (SS - 1);
                    int h = colg >> 6, d = colg & (DK - 1);
                    *(float2*)&Y[(((size_t)(b * NHEADS + h)) * SS + srow) * DK + d] = o2;
                } else {
                    *(float2*)&Y[(size_t)m * DMODEL + colg] = o2;
                }
            }
        }
}

__global__ __launch_bounds__(256) void gemm_qkv_tc(
    const float* __restrict__ bq, const float* __restrict__ bk, const float* __restrict__ bv)
{
    int z = blockIdx.z;
    const float* bias = (z == 0) ? bq : (z == 1) ? bk : bv;
    float*       Y    = (z == 0) ? g_Q : (z == 1) ? g_K : g_V;
    gemm_tc_body<true>(g_Ah + (size_t)z * APAIRS, g_Al + (size_t)z * APAIRS,
                       g_Wh + (size_t)z * WPAIRS, g_Wl + (size_t)z * WPAIRS,
                       bias, Y);
}

__global__ __launch_bounds__(256) void gemm_out_tc(
    const float* __restrict__ bo, float* __restrict__ out)
{
    gemm_tc_body<false>(g_Chp, g_Clp,
                        g_Wh + (size_t)3 * WPAIRS, g_Wl + (size_t)3 * WPAIRS,
                        bo, out);
}

// ===========================================================================
// Flash attention via mma.sync split-bf16 (unchanged from passing R8 version).
// ===========================================================================
#define ATTN_SMEM (64 * 1024)

__global__ __launch_bounds__(256) void attn_tc_kernel()
{
    extern __shared__ char sma[];
    char* sQh = sma;
    char* sQl = sma + 16384;
    char* sKh = sma + 32768;
    char* sKl = sma + 40960;
    char* sVh = sma + 49152;
    char* sVl = sma + 57344;
    const uint32_t aQh = smem_u32(sQh), aQl = smem_u32(sQl);
    const uint32_t aKh = smem_u32(sKh), aKl = smem_u32(sKl);
    const uint32_t aVh = smem_u32(sVh), aVl = smem_u32(sVl);

    const int tid = threadIdx.x;
    const int wid = tid >> 5, l = tid & 31;
    const int t  = (int)gridDim.x - 1 - (int)blockIdx.x;   // heavy tiles first
    const int bh = blockIdx.y;
    const int m0 = t * 128;

    const float* Qg  = g_Q + (size_t)bh * SS * DK + (size_t)m0 * DK;
    const float* Kg0 = g_K + (size_t)bh * SS * DK;
    const float* Vg0 = g_V + (size_t)bh * SS * DK;

    const int a_row_off = ((l >> 3) & 1) * 8 + (l & 7);
    const int a_chk_off = (l >> 4);
    const int b_row_off = ((l >> 4) & 1) * 8 + (l & 7);
    const int b_chk_off = ((l >> 3) & 1);
    const int v_row_off = ((l >> 3) & 1) * 8 + (l & 7);
    const int v_chk_off = (l >> 4);

#pragma unroll
    for (int it = 0; it < 16; it++) {
        int idx = tid + it * 256;
        int r = idx >> 5, c2 = idx & 31;
        float2 v = *(const float2*)(Qg + (size_t)r * DK + c2 * 2);
        v.x *= 0.125f; v.y *= 0.125f;
        uint32_t hp, lp;
        split2(v, hp, lp);
        uint32_t off = swz(r, c2 >> 2) + ((c2 & 3) << 2);
        *(uint32_t*)(sQh + off) = hp;
        *(uint32_t*)(sQl + off) = lp;
    }
    __syncthreads();

    uint32_t qh[4][4], ql[4][4];
#pragma unroll
    for (int ks = 0; ks < 4; ks++) {
        uint32_t o = swz(wid * 16 + a_row_off, ks * 2 + a_chk_off);
        ldsm_x4(qh[ks][0], qh[ks][1], qh[ks][2], qh[ks][3], aQh + o);
        ldsm_x4(ql[ks][0], ql[ks][1], ql[ks][2], ql[ks][3], aQl + o);
    }

    float o[8][4];
#pragma unroll
    for (int ng = 0; ng < 8; ng++)
#pragma unroll
        for (int i = 0; i < 4; i++) o[ng][i] = 0.f;
    float mA = -INFINITY, mB = -INFINITY, lA = 0.f, lB = 0.f;

    const int rowA = m0 + wid * 16 + (l >> 2);
    const int rowB = rowA + 8;
    const int kmax = 2 * t + 1;

    for (int kt = 0; kt <= kmax; kt++) {
        const float* Kg = Kg0 + (size_t)kt * 64 * DK;
        const float* Vg = Vg0 + (size_t)kt * 64 * DK;

        if (kt) __syncthreads();
#pragma unroll
        for (int it = 0; it < 8; it++) {
            int idx = tid + it * 256;
            int r = idx >> 5, c2 = idx & 31;
            uint32_t off = swz(r, c2 >> 2) + ((c2 & 3) << 2);
            uint32_t hp, lp;
            split2(*(const float2*)(Kg + (size_t)r * DK + c2 * 2), hp, lp);
            *(uint32_t*)(sKh + off) = hp;
            *(uint32_t*)(sKl + off) = lp;
            split2(*(const float2*)(Vg + (size_t)r * DK + c2 * 2), hp, lp);
            *(uint32_t*)(sVh + off) = hp;
            *(uint32_t*)(sVl + off) = lp;
        }
        __syncthreads();

        float s[8][4];
#pragma unroll
        for (int ng = 0; ng < 8; ng++)
#pragma unroll
            for (int i = 0; i < 4; i++) s[ng][i] = 0.f;
#pragma unroll
        for (int ks = 0; ks < 4; ks++) {
            uint32_t kbh[8][2], kbl[8][2];
#pragma unroll
            for (int g2 = 0; g2 < 4; g2++) {
                uint32_t off = swz(g2 * 16 + b_row_off, ks * 2 + b_chk_off);
                ldsm_x4(kbh[g2*2][0], kbh[g2*2][1], kbh[g2*2+1][0], kbh[g2*2+1][1], aKh + off);
                ldsm_x4(kbl[g2*2][0], kbl[g2*2][1], kbl[g2*2+1][0], kbl[g2*2+1][1], aKl + off);
            }
#pragma unroll
            for (int ng = 0; ng < 8; ng++) {
                mma_bf16(s[ng], qh[ks], kbh[ng]);
                mma_bf16(s[ng], qh[ks], kbl[ng]);
                mma_bf16(s[ng], ql[ks], kbh[ng]);
            }
        }

        if (kt >= 2 * t) {
#pragma unroll
            for (int ng = 0; ng < 8; ng++) {
                int cb = kt * 64 + ng * 8 + (l & 3) * 2;
                if (cb     > rowA) s[ng][0] = -INFINITY;
                if (cb + 1 > rowA) s[ng][1] = -INFINITY;
                if (cb     > rowB) s[ng][2] = -INFINITY;
                if (cb + 1 > rowB) s[ng][3] = -INFINITY;
            }
        }

        float mxA = -INFINITY, mxB = -INFINITY;
#pragma unroll
        for (int ng = 0; ng < 8; ng++) {
            mxA = fmaxf(mxA, fmaxf(s[ng][0], s[ng][1]));
            mxB = fmaxf(mxB, fmaxf(s[ng][2], s[ng][3]));
        }
#pragma unroll
        for (int off = 1; off <= 2; off <<= 1) {
            mxA = fmaxf(mxA, __shfl_xor_sync(0xffffffffu, mxA, off));
            mxB = fmaxf(mxB, __shfl_xor_sync(0xffffffffu, mxB, off));
        }
        float mnA = fmaxf(mA, mxA), mnB = fmaxf(mB, mxB);
        float corrA = __expf(mA - mnA), corrB = __expf(mB - mnB);
        mA = mnA; mB = mnB;

        float suA = 0.f, suB = 0.f;
#pragma unroll
        for (int ng = 0; ng < 8; ng++) {
            s[ng][0] = __expf(s[ng][0] - mA);
            s[ng][1] = __expf(s[ng][1] - mA);
            s[ng][2] = __expf(s[ng][2] - mB);
            s[ng][3] = __expf(s[ng][3] - mB);
            suA += s[ng][0] + s[ng][1];
            suB += s[ng][2] + s[ng][3];
        }
#pragma unroll
        for (int off = 1; off <= 2; off <<= 1) {
            suA += __shfl_xor_sync(0xffffffffu, suA, off);
            suB += __shfl_xor_sync(0xffffffffu, suB, off);
        }
        lA = lA * corrA + suA;
        lB = lB * corrB + suB;
#pragma unroll
        for (int ng = 0; ng < 8; ng++) {
            o[ng][0] *= corrA; o[ng][1] *= corrA;
            o[ng][2] *= corrB; o[ng][3] *= corrB;
        }

        uint32_t ph[4][4], pl[4][4];
#pragma unroll
        for (int kk = 0; kk < 4; kk++) {
            split2(make_float2(s[2*kk  ][0], s[2*kk  ][1]), ph[kk][0], pl[kk][0]);
            split2(make_float2(s[2*kk  ][2], s[2*kk  ][3]), ph[kk][1], pl[kk][1]);
            split2(make_float2(s[2*kk+1][0], s[2*kk+1][1]), ph[kk][2], pl[kk][2]);
            split2(make_float2(s[2*kk+1][2], s[2*kk+1][3]), ph[kk][3], pl[kk][3]);
        }

#pragma unroll
        for (int kk = 0; kk < 4; kk++) {
            uint32_t vbh[8][2], vbl[8][2];
#pragma unroll
            for (int g2 = 0; g2 < 4; g2++) {
                uint32_t off = swz(kk * 16 + v_row_off, g2 * 2 + v_chk_off);
                ldsm_x4_t(vbh[g2*2][0], vbh[g2*2][1], vbh[g2*2+1][0], vbh[g2*2+1][1], aVh + off);
                ldsm_x4_t(vbl[g2*2][0], vbl[g2*2][1], vbl[g2*2+1][0], vbl[g2*2+1][1], aVl + off);
            }
#pragma unroll
            for (int ng = 0; ng < 8; ng++) {
                mma_bf16(o[ng], ph[kk], vbh[ng]);
                mma_bf16(o[ng], ph[kk], vbl[ng]);
                mma_bf16(o[ng], pl[kk], vbh[ng]);
            }
        }
    }

    const float invA = 1.f / lA, invB = 1.f / lB;
    const int b = bh / NHEADS, h = bh % NHEADS;
    float* dstA = &g_C[((size_t)(b * SS + rowA)) * DMODEL + h * DK];
    float* dstB = &g_C[((size_t)(b * SS + rowB)) * DMODEL + h * DK];
#pragma unroll
    for (int ng = 0; ng < 8; ng++) {
        int col = ng * 8 + (l & 3) * 2;
        float2 wa; wa.x = o[ng][0] * invA; wa.y = o[ng][1] * invA;
        float2 wb; wb.x = o[ng][2] * invB; wb.y = o[ng][3] * invB;
        *(float2*)(dstA + col) = wa;
        *(float2*)(dstB + col) = wb;
    }
}

// ---------------------------------------------------------------------------

extern "C" void kernel_launch(void* const* d_in, const int* in_sizes, int n_in,
                              void* d_out, int out_size)
{
    const float* q  = (const float*)d_in[0];
    const float* k  = (const float*)d_in[1];
    const float* v  = (const float*)d_in[2];
    const float* Wq = (const float*)d_in[3];
    const float* bq = (const float*)d_in[4];
    const float* Wk = (const float*)d_in[5];
    const float* bk = (const float*)d_in[6];
    const float* Wv = (const float*)d_in[7];
    const float* bv = (const float*)d_in[8];
    const float* Wo = (const float*)d_in[9];
    const float* bo = (const float*)d_in[10];
    // d_in[11] = mask (exact tril; handled as causal structure in-kernel)

    float* out = (float*)d_out;

    cudaFuncSetAttribute(gemm_qkv_tc,    cudaFuncAttributeMaxDynamicSharedMemorySize, GEMM_SMEM);
    cudaFuncSetAttribute(gemm_out_tc,    cudaFuncAttributeMaxDynamicSharedMemorySize, GEMM_SMEM);
    cudaFuncSetAttribute(attn_tc_kernel, cudaFuncAttributeMaxDynamicSharedMemorySize, ATTN_SMEM);

    // 0) pre-split inputs + weights to bf16 hi/lo
    convert_split_kernel<<<dim3(APAIRS/256, 7), 256>>>(q, k, v, Wq, Wk, Wv, Wo);

    // 1) QKV projections (cp.async double-buffered, MMA-only inner loop)
    gemm_qkv_tc<<<dim3(DMODEL/128, NTOK/128, 3), 256, GEMM_SMEM>>>(bq, bk, bv);

    // 2) Flash attention (causal, mma.sync split-bf16)
    attn_tc_kernel<<<dim3(SS/128, BB*NHEADS), 256, ATTN_SMEM>>>();

    // 3) split context to bf16 hi/lo, then output projection into d_out
    convert_c_kernel<<<APAIRS/256, 256>>>();
    gemm_out_tc<<<dim3(DMODEL/128, NTOK/128), 256, GEMM_SMEM>>>(bo, out);
}

// round 13
// speedup vs baseline: 1.0875x; 1.0875x over previous
#include <cuda_runtime.h>
#include <cuda_bf16.h>
#include <math.h>
#include <stdint.h>

#define DMODEL 1024
#define NHEADS 16
#define DK 64
#define BB 2
#define SS 2048
#define NTOK (BB*SS)

// fp32 scratch
__device__ float g_Q[NTOK*DMODEL];   // [B*H, S, DK] head-major
__device__ float g_K[NTOK*DMODEL];   // [B*H, S, DK]
__device__ float g_V[NTOK*DMODEL];   // [B*H, S, DK]

// pre-split bf16 operands (bf16x2 packs as uint32)
#define APAIRS (NTOK*DMODEL/2)
#define WPAIRS (DMODEL*DMODEL/2)
__device__ uint32_t g_Ah[3*APAIRS];  // q,k,v hi
__device__ uint32_t g_Al[3*APAIRS];  // q,k,v lo
__device__ uint32_t g_Wh[4*WPAIRS];  // Wq,Wk,Wv,Wo hi
__device__ uint32_t g_Wl[4*WPAIRS];  // lo
__device__ uint32_t g_Chp[APAIRS];   // context hi (written by attention epilogue)
__device__ uint32_t g_Clp[APAIRS];   // context lo

// ===========================================================================
// helpers
// ===========================================================================
__device__ __forceinline__ uint32_t smem_u32(const void* p) {
    uint32_t a;
    asm("{ .reg .u64 t; cvta.to.shared.u64 t, %1; cvt.u32.u64 %0, t; }"
        : "=r"(a) : "l"(p));
    return a;
}

__device__ __forceinline__ void ldsm_x4(uint32_t& r0, uint32_t& r1,
                                        uint32_t& r2, uint32_t& r3, uint32_t addr) {
    asm volatile("ldmatrix.sync.aligned.m8n8.x4.shared.b16 {%0,%1,%2,%3}, [%4];"
                 : "=r"(r0), "=r"(r1), "=r"(r2), "=r"(r3) : "r"(addr));
}

__device__ __forceinline__ void ldsm_x4_t(uint32_t& r0, uint32_t& r1,
                                          uint32_t& r2, uint32_t& r3, uint32_t addr) {
    asm volatile("ldmatrix.sync.aligned.m8n8.x4.trans.shared.b16 {%0,%1,%2,%3}, [%4];"
                 : "=r"(r0), "=r"(r1), "=r"(r2), "=r"(r3) : "r"(addr));
}

__device__ __forceinline__ void mma_bf16(float* c, const uint32_t* a, const uint32_t* b) {
    asm volatile(
        "mma.sync.aligned.m16n8k16.row.col.f32.bf16.bf16.f32 "
        "{%0,%1,%2,%3}, {%4,%5,%6,%7}, {%8,%9}, {%0,%1,%2,%3};"
        : "+f"(c[0]), "+f"(c[1]), "+f"(c[2]), "+f"(c[3])
        : "r"(a[0]), "r"(a[1]), "r"(a[2]), "r"(a[3]), "r"(b[0]), "r"(b[1]));
}

__device__ __forceinline__ void split2(float2 v, uint32_t& hp, uint32_t& lp) {
    asm("cvt.rn.bf16x2.f32 %0, %1, %2;" : "=r"(hp) : "f"(v.y), "f"(v.x));
    float h0 = __uint_as_float(hp << 16);
    float h1 = __uint_as_float(hp & 0xffff0000u);
    asm("cvt.rn.bf16x2.f32 %0, %1, %2;" : "=r"(lp) : "f"(v.y - h1), "f"(v.x - h0));
}

__device__ __forceinline__ uint32_t swz(int row, int chunk) {
    return (uint32_t)(row * 128 + ((chunk ^ (row & 7)) << 4));
}

#define CP16(dst, src) \
    asm volatile("cp.async.cg.shared.global [%0], [%1], 16;" \
        :: "r"(dst), "l"(src) : "memory")
#define CP_COMMIT() asm volatile("cp.async.commit_group;" ::: "memory")
#define CP_WAIT1()  asm volatile("cp.async.wait_group 1;" ::: "memory")
#define CP_WAIT0()  asm volatile("cp.async.wait_group 0;" ::: "memory")

// ===========================================================================
// Prep: split fp32 -> bf16 hi/lo in global (vectorized: 4 pairs / thread)
// ===========================================================================
__global__ __launch_bounds__(256) void convert_split_kernel(
    const float* __restrict__ q,  const float* __restrict__ k,  const float* __restrict__ v,
    const float* __restrict__ Wq, const float* __restrict__ Wk, const float* __restrict__ Wv,
    const float* __restrict__ Wo)
{
    const int z = blockIdx.y;
    const float* src;
    uint32_t *dh, *dl;
    int npairs;
    if (z < 3) {
        src = (z == 0) ? q : (z == 1) ? k : v;
        dh = g_Ah + (size_t)z * APAIRS; dl = g_Al + (size_t)z * APAIRS;
        npairs = APAIRS;
    } else {
        src = (z == 3) ? Wq : (z == 4) ? Wk : (z == 5) ? Wv : Wo;
        dh = g_Wh + (size_t)(z - 3) * WPAIRS; dl = g_Wl + (size_t)(z - 3) * WPAIRS;
        npairs = WPAIRS;
    }
    int i = (blockIdx.x * 256 + threadIdx.x) * 4;   // pair index, multiple of 4
    if (i < npairs) {
        const float4* s4 = (const float4*)src;
        float4 a  = s4[i >> 1];
        float4 b2 = s4[(i >> 1) + 1];
        uint4 h4, l4;
        split2(make_float2(a.x,  a.y),  h4.x, l4.x);
        split2(make_float2(a.z,  a.w),  h4.y, l4.y);
        split2(make_float2(b2.x, b2.y), h4.z, l4.z);
        split2(make_float2(b2.z, b2.w), h4.w, l4.w);
        ((uint4*)dh)[i >> 2] = h4;
        ((uint4*)dl)[i >> 2] = l4;
    }
}

// ===========================================================================
// Tensor-core GEMM on pre-split bf16: Y = X @ W^T + b.
// CTA tile 256x128, BK=64, 512 threads (16 warps, 4m x 4n), warp tile 64x32.
// Stage = Ahi(32K)|Alo(32K)|Bhi(16K)|Blo(16K) = 96 KB; 2 stages = 192 KB.
// ===========================================================================
#define NCHUNK 16
#define A_HI_OFF 0
#define A_LO_OFF 32768
#define B_HI_OFF 65536
#define B_LO_OFF 81920
#define STAGE_B  98304
#define GEMM_SMEM (2 * STAGE_B)      // 192 KB

template<bool SPLIT>
__device__ __forceinline__ void gemm_tc_body(const uint32_t* __restrict__ Ah,
                                             const uint32_t* __restrict__ Al,
                                             const uint32_t* __restrict__ Bh,
                                             const uint32_t* __restrict__ Bl,
                                             const float* __restrict__ bias,
                                             float* __restrict__ Y)
{
    extern __shared__ char smc[];
    const uint32_t sbase = smem_u32(smc);

    const int tid = threadIdx.x;
    const int wid = tid >> 5, l = tid & 31;
    const int warp_m = (wid & 3) * 64;        // 0/64/128/192
    const int warp_n = (wid >> 2) * 32;       // 0/32/64/96
    const int m0 = blockIdx.y * 256, n0 = blockIdx.x * 128;

    // byte bases (row stride = 2048 B)
    const char* Ahb = (const char*)Ah + (size_t)m0 * 2048;
    const char* Alb = (const char*)Al + (size_t)m0 * 2048;
    const char* Bhb = (const char*)Bh + (size_t)n0 * 2048;
    const char* Blb = (const char*)Bl + (size_t)n0 * 2048;

    float c[4][4][4];
#pragma unroll
    for (int i = 0; i < 4; i++)
#pragma unroll
        for (int j = 0; j < 4; j++)
#pragma unroll
            for (int t = 0; t < 4; t++) c[i][j][t] = 0.f;

    const int a_row_off = ((l >> 3) & 1) * 8 + (l & 7);
    const int a_chk_off = (l >> 4);
    const int b_row_off = ((l >> 4) & 1) * 8 + (l & 7);
    const int b_chk_off = ((l >> 3) & 1);

    auto issue = [&](int s, int ch) {
        const uint32_t sb = sbase + s * STAGE_B;
        const size_t coff = (size_t)ch * 128;   // 64 bf16 cols = 128 B
#pragma unroll
        for (int it = 0; it < 4; it++) {        // A: 256 rows x 8 chunks
            int idx = tid + it * 512;
            int row = idx >> 3, chunk = idx & 7;
            uint32_t d = swz(row, chunk);
            size_t so = (size_t)row * 2048 + coff + (size_t)(chunk << 4);
            CP16(sb + A_HI_OFF + d, Ahb + so);
            CP16(sb + A_LO_OFF + d, Alb + so);
        }
#pragma unroll
        for (int it = 0; it < 2; it++) {        // B: 128 rows x 8 chunks
            int idx = tid + it * 512;
            int row = idx >> 3, chunk = idx & 7;
            uint32_t d = swz(row, chunk);
            size_t so = (size_t)row * 2048 + coff + (size_t)(chunk << 4);
            CP16(sb + B_HI_OFF + d, Bhb + so);
            CP16(sb + B_LO_OFF + d, Blb + so);
        }
        CP_COMMIT();
    };

    issue(0, 0);

    for (int ch = 0; ch < NCHUNK; ch++) {
        const int cur = ch & 1;
        if (ch + 1 < NCHUNK) { issue(cur ^ 1, ch + 1); CP_WAIT1(); }
        else                 { CP_WAIT0(); }
        __syncthreads();

        const uint32_t aAhi = sbase + cur * STAGE_B + A_HI_OFF;
        const uint32_t aAlo = sbase + cur * STAGE_B + A_LO_OFF;
        const uint32_t aBhi = sbase + cur * STAGE_B + B_HI_OFF;
        const uint32_t aBlo = sbase + cur * STAGE_B + B_LO_OFF;

#pragma unroll
        for (int ks = 0; ks < 4; ks++) {
            uint32_t ahi[4][4], alo[4][4], bhi[4][2], blo[4][2];
#pragma unroll
            for (int mi = 0; mi < 4; mi++) {
                int row = warp_m + mi * 16 + a_row_off;
                uint32_t o = swz(row, ks * 2 + a_chk_off);
                ldsm_x4(ahi[mi][0], ahi[mi][1], ahi[mi][2], ahi[mi][3], aAhi + o);
                ldsm_x4(alo[mi][0], alo[mi][1], alo[mi][2], alo[mi][3], aAlo + o);
            }
#pragma unroll
            for (int nj = 0; nj < 2; nj++) {
                int row = warp_n + nj * 16 + b_row_off;
                uint32_t o = swz(row, ks * 2 + b_chk_off);
                ldsm_x4(bhi[nj*2][0], bhi[nj*2][1], bhi[nj*2+1][0], bhi[nj*2+1][1], aBhi + o);
                ldsm_x4(blo[nj*2][0], blo[nj*2][1], blo[nj*2+1][0], blo[nj*2+1][1], aBlo + o);
            }
#pragma unroll
            for (int mi = 0; mi < 4; mi++)
#pragma unroll
                for (int ni = 0; ni < 4; ni++) {
                    mma_bf16(c[mi][ni], ahi[mi], bhi[ni]);
                    mma_bf16(c[mi][ni], ahi[mi], blo[ni]);
                    mma_bf16(c[mi][ni], alo[mi], bhi[ni]);
                }
        }
        __syncthreads();
    }

#pragma unroll
    for (int mi = 0; mi < 4; mi++)
#pragma unroll
        for (int ni = 0; ni < 4; ni++) {
            int colg = n0 + warp_n + ni * 8 + (l & 3) * 2;
            float2 bv = *(const float2*)&bias[colg];
            int r0 = m0 + warp_m + mi * 16 + (l >> 2);
#pragma unroll
            for (int half = 0; half < 2; half++) {
                int m = r0 + half * 8;
                float2 o2;
                o2.x = c[mi][ni][half * 2 + 0] + bv.x;
                o2.y = c[mi][ni][half * 2 + 1] + bv.y;
                if (SPLIT) {
                    int b = m >> 11, srow = m & (SS - 1);
                    int h = colg >> 6, d = colg & (DK - 1);
                    *(float2*)&Y[(((size_t)(b * NHEADS + h)) * SS + srow) * DK + d] = o2;
                } else {
                    *(float2*)&Y[(size_t)m * DMODEL + colg] = o2;
                }
            }
        }
}

__global__ __launch_bounds__(512) void gemm_qkv_tc(
    const float* __restrict__ bq, const float* __restrict__ bk, const float* __restrict__ bv)
{
    int z = blockIdx.z;
    const float* bias = (z == 0) ? bq : (z == 1) ? bk : bv;
    float*       Y    = (z == 0) ? g_Q : (z == 1) ? g_K : g_V;
    gemm_tc_body<true>(g_Ah + (size_t)z * APAIRS, g_Al + (size_t)z * APAIRS,
                       g_Wh + (size_t)z * WPAIRS, g_Wl + (size_t)z * WPAIRS,
                       bias, Y);
}

__global__ __launch_bounds__(512) void gemm_out_tc(
    const float* __restrict__ bo, float* __restrict__ out)
{
    gemm_tc_body<false>(g_Chp, g_Clp,
                        g_Wh + (size_t)3 * WPAIRS, g_Wl + (size_t)3 * WPAIRS,
                        bo, out);
}

// ===========================================================================
// Flash attention via mma.sync split-bf16 (R8-proven), epilogue now writes
// the context pre-split (g_Chp/g_Clp) so no separate convert pass is needed.
// ===========================================================================
#define ATTN_SMEM (64 * 1024)

__global__ __launch_bounds__(256) void attn_tc_kernel()
{
    extern __shared__ char sma[];
    char* sQh = sma;
    char* sQl = sma + 16384;
    char* sKh = sma + 32768;
    char* sKl = sma + 40960;
    char* sVh = sma + 49152;
    char* sVl = sma + 57344;
    const uint32_t aQh = smem_u32(sQh), aQl = smem_u32(sQl);
    const uint32_t aKh = smem_u32(sKh), aKl = smem_u32(sKl);
    const uint32_t aVh = smem_u32(sVh), aVl = smem_u32(sVl);

    const int tid = threadIdx.x;
    const int wid = tid >> 5, l = tid & 31;
    const int t  = (int)gridDim.x - 1 - (int)blockIdx.x;   // heavy tiles first
    const int bh = blockIdx.y;
    const int m0 = t * 128;

    const float* Qg  = g_Q + (size_t)bh * SS * DK + (size_t)m0 * DK;
    const float* Kg0 = g_K + (size_t)bh * SS * DK;
    const float* Vg0 = g_V + (size_t)bh * SS * DK;

    const int a_row_off = ((l >> 3) & 1) * 8 + (l & 7);
    const int a_chk_off = (l >> 4);
    const int b_row_off = ((l >> 4) & 1) * 8 + (l & 7);
    const int b_chk_off = ((l >> 3) & 1);
    const int v_row_off = ((l >> 3) & 1) * 8 + (l & 7);
    const int v_chk_off = (l >> 4);

#pragma unroll
    for (int it = 0; it < 16; it++) {
        int idx = tid + it * 256;
        int r = idx >> 5, c2 = idx & 31;
        float2 v = *(const float2*)(Qg + (size_t)r * DK + c2 * 2);
        v.x *= 0.125f; v.y *= 0.125f;
        uint32_t hp, lp;
        split2(v, hp, lp);
        uint32_t off = swz(r, c2 >> 2) + ((c2 & 3) << 2);
        *(uint32_t*)(sQh + off) = hp;
        *(uint32_t*)(sQl + off) = lp;
    }
    __syncthreads();

    uint32_t qh[4][4], ql[4][4];
#pragma unroll
    for (int ks = 0; ks < 4; ks++) {
        uint32_t o = swz(wid * 16 + a_row_off, ks * 2 + a_chk_off);
        ldsm_x4(qh[ks][0], qh[ks][1], qh[ks][2], qh[ks][3], aQh + o);
        ldsm_x4(ql[ks][0], ql[ks][1], ql[ks][2], ql[ks][3], aQl + o);
    }

    float o[8][4];
#pragma unroll
    for (int ng = 0; ng < 8; ng++)
#pragma unroll
        for (int i = 0; i < 4; i++) o[ng][i] = 0.f;
    float mA = -INFINITY, mB = -INFINITY, lA = 0.f, lB = 0.f;

    const int rowA = m0 + wid * 16 + (l >> 2);
    const int rowB = rowA + 8;
    const int kmax = 2 * t + 1;

    for (int kt = 0; kt <= kmax; kt++) {
        const float* Kg = Kg0 + (size_t)kt * 64 * DK;
        const float* Vg = Vg0 + (size_t)kt * 64 * DK;

        if (kt) __syncthreads();
#pragma unroll
        for (int it = 0; it < 8; it++) {
            int idx = tid + it * 256;
            int r = idx >> 5, c2 = idx & 31;
            uint32_t off = swz(r, c2 >> 2) + ((c2 & 3) << 2);
            uint32_t hp, lp;
            split2(*(const float2*)(Kg + (size_t)r * DK + c2 * 2), hp, lp);
            *(uint32_t*)(sKh + off) = hp;
            *(uint32_t*)(sKl + off) = lp;
            split2(*(const float2*)(Vg + (size_t)r * DK + c2 * 2), hp, lp);
            *(uint32_t*)(sVh + off) = hp;
            *(uint32_t*)(sVl + off) = lp;
        }
        __syncthreads();

        float s[8][4];
#pragma unroll
        for (int ng = 0; ng < 8; ng++)
#pragma unroll
            for (int i = 0; i < 4; i++) s[ng][i] = 0.f;
#pragma unroll
        for (int ks = 0; ks < 4; ks++) {
            uint32_t kbh[8][2], kbl[8][2];
#pragma unroll
            for (int g2 = 0; g2 < 4; g2++) {
                uint32_t off = swz(g2 * 16 + b_row_off, ks * 2 + b_chk_off);
                ldsm_x4(kbh[g2*2][0], kbh[g2*2][1], kbh[g2*2+1][0], kbh[g2*2+1][1], aKh + off);
                ldsm_x4(kbl[g2*2][0], kbl[g2*2][1], kbl[g2*2+1][0], kbl[g2*2+1][1], aKl + off);
            }
#pragma unroll
            for (int ng = 0; ng < 8; ng++) {
                mma_bf16(s[ng], qh[ks], kbh[ng]);
                mma_bf16(s[ng], qh[ks], kbl[ng]);
                mma_bf16(s[ng], ql[ks], kbh[ng]);
            }
        }

        if (kt >= 2 * t) {
#pragma unroll
            for (int ng = 0; ng < 8; ng++) {
                int cb = kt * 64 + ng * 8 + (l & 3) * 2;
                if (cb     > rowA) s[ng][0] = -INFINITY;
                if (cb + 1 > rowA) s[ng][1] = -INFINITY;
                if (cb     > rowB) s[ng][2] = -INFINITY;
                if (cb + 1 > rowB) s[ng][3] = -INFINITY;
            }
        }

        float mxA = -INFINITY, mxB = -INFINITY;
#pragma unroll
        for (int ng = 0; ng < 8; ng++) {
            mxA = fmaxf(mxA, fmaxf(s[ng][0], s[ng][1]));
            mxB = fmaxf(mxB, fmaxf(s[ng][2], s[ng][3]));
        }
#pragma unroll
        for (int off = 1; off <= 2; off <<= 1) {
            mxA = fmaxf(mxA, __shfl_xor_sync(0xffffffffu, mxA, off));
            mxB = fmaxf(mxB, __shfl_xor_sync(0xffffffffu, mxB, off));
        }
        float mnA = fmaxf(mA, mxA), mnB = fmaxf(mB, mxB);
        float corrA = __expf(mA - mnA), corrB = __expf(mB - mnB);
        mA = mnA; mB = mnB;

        float suA = 0.f, suB = 0.f;
#pragma unroll
        for (int ng = 0; ng < 8; ng++) {
            s[ng][0] = __expf(s[ng][0] - mA);
            s[ng][1] = __expf(s[ng][1] - mA);
            s[ng][2] = __expf(s[ng][2] - mB);
            s[ng][3] = __expf(s[ng][3] - mB);
            suA += s[ng][0] + s[ng][1];
            suB += s[ng][2] + s[ng][3];
        }
#pragma unroll
        for (int off = 1; off <= 2; off <<= 1) {
            suA += __shfl_xor_sync(0xffffffffu, suA, off);
            suB += __shfl_xor_sync(0xffffffffu, suB, off);
        }
        lA = lA * corrA + suA;
        lB = lB * corrB + suB;
#pragma unroll
        for (int ng = 0; ng < 8; ng++) {
            o[ng][0] *= corrA; o[ng][1] *= corrA;
            o[ng][2] *= corrB; o[ng][3] *= corrB;
        }

        uint32_t ph[4][4], pl[4][4];
#pragma unroll
        for (int kk = 0; kk < 4; kk++) {
            split2(make_float2(s[2*kk  ][0], s[2*kk  ][1]), ph[kk][0], pl[kk][0]);
            split2(make_float2(s[2*kk  ][2], s[2*kk  ][3]), ph[kk][1], pl[kk][1]);
            split2(make_float2(s[2*kk+1][0], s[2*kk+1][1]), ph[kk][2], pl[kk][2]);
            split2(make_float2(s[2*kk+1][2], s[2*kk+1][3]), ph[kk][3], pl[kk][3]);
        }

#pragma unroll
        for (int kk = 0; kk < 4; kk++) {
            uint32_t vbh[8][2], vbl[8][2];
#pragma unroll
            for (int g2 = 0; g2 < 4; g2++) {
                uint32_t off = swz(kk * 16 + v_row_off, g2 * 2 + v_chk_off);
                ldsm_x4_t(vbh[g2*2][0], vbh[g2*2][1], vbh[g2*2+1][0], vbh[g2*2+1][1], aVh + off);
                ldsm_x4_t(vbl[g2*2][0], vbl[g2*2][1], vbl[g2*2+1][0], vbl[g2*2+1][1], aVl + off);
            }
#pragma unroll
            for (int ng = 0; ng < 8; ng++) {
                mma_bf16(o[ng], ph[kk], vbh[ng]);
                mma_bf16(o[ng], ph[kk], vbl[ng]);
                mma_bf16(o[ng], pl[kk], vbh[ng]);
            }
        }
    }

    // ---- epilogue: normalize and write ctx PRE-SPLIT (hi/lo bf16 packs) ----
    const float invA = 1.f / lA, invB = 1.f / lB;
    const int b = bh / NHEADS, h = bh % NHEADS;
#pragma unroll
    for (int ng = 0; ng < 8; ng++) {
        int col = ng * 8 + (l & 3) * 2;
        uint32_t hp, lp;
        split2(make_float2(o[ng][0] * invA, o[ng][1] * invA), hp, lp);
        size_t pidx = (((size_t)(b * SS + rowA)) * DMODEL + h * DK + col) >> 1;
        g_Chp[pidx] = hp; g_Clp[pidx] = lp;
        split2(make_float2(o[ng][2] * invB, o[ng][3] * invB), hp, lp);
        pidx = (((size_t)(b * SS + rowB)) * DMODEL + h * DK + col) >> 1;
        g_Chp[pidx] = hp; g_Clp[pidx] = lp;
    }
}

// ---------------------------------------------------------------------------

extern "C" void kernel_launch(void* const* d_in, const int* in_sizes, int n_in,
                              void* d_out, int out_size)
{
    const float* q  = (const float*)d_in[0];
    const float* k  = (const float*)d_in[1];
    const float* v  = (const float*)d_in[2];
    const float* Wq = (const float*)d_in[3];
    const float* bq = (const float*)d_in[4];
    const float* Wk = (const float*)d_in[5];
    const float* bk = (const float*)d_in[6];
    const float* Wv = (const float*)d_in[7];
    const float* bv = (const float*)d_in[8];
    const float* Wo = (const float*)d_in[9];
    const float* bo = (const float*)d_in[10];
    // d_in[11] = mask (exact tril; handled as causal structure in-kernel)

    float* out = (float*)d_out;

    cudaFuncSetAttribute(gemm_qkv_tc,    cudaFuncAttributeMaxDynamicSharedMemorySize, GEMM_SMEM);
    cudaFuncSetAttribute(gemm_out_tc,    cudaFuncAttributeMaxDynamicSharedMemorySize, GEMM_SMEM);
    cudaFuncSetAttribute(attn_tc_kernel, cudaFuncAttributeMaxDynamicSharedMemorySize, ATTN_SMEM);

    // 0) pre-split inputs + weights to bf16 hi/lo (vectorized)
    convert_split_kernel<<<dim3(APAIRS/1024, 7), 256>>>(q, k, v, Wq, Wk, Wv, Wo);

    // 1) QKV projections (256x128 tile, cp.async double-buffered, MMA-only loop)
    gemm_qkv_tc<<<dim3(DMODEL/128, NTOK/256, 3), 512, GEMM_SMEM>>>(bq, bk, bv);

    // 2) Flash attention (causal, mma.sync split-bf16; writes pre-split ctx)
    attn_tc_kernel<<<dim3(SS/128, BB*NHEADS), 256, ATTN_SMEM>>>();

    // 3) Output projection straight into d_out (single wave: 128 CTAs)
    gemm_out_tc<<<dim3(DMODEL/128, NTOK/256), 512, GEMM_SMEM>>>(bo, out);
}